// round 2
// baseline (speedup 1.0000x reference)
#include <cuda_runtime.h>
#include <cuda_bf16.h>
#include <math.h>

#define NN 6000
#define EE 100000
#define ET (EE + NN)

// ---------------- scratch (static __device__, no allocs) ----------------
__device__ float g_x[NN * 64];          // layer activations (in-place per layer)
__device__ float g_base[NN * 64];       // root term + bias
__device__ float g_hr[2 * NN * 64];     // per-relation transformed features
__device__ float g_s[2 * NN * 64];      // per-relation segment sums
__device__ float g_Wcat[64 * 128];      // [I, 2*O] relation weights
__device__ int   g_cnt[2 * NN];
__device__ float g_rinv[2 * NN];
__device__ float g_h[NN * 512];         // GAT transformed features
__device__ float g_asv[NN], g_adv[NN];
__device__ float g_alpha[ET];           // leaky-relu'd logits, then exp() in place
__device__ float g_denom[NN];
__device__ unsigned g_amax[NN];
__device__ float g_o512[NN * 512];      // GAT output
__device__ float g_A[NN * 128], g_B[NN * 128];

// ---------------- helpers ----------------
__device__ __forceinline__ unsigned enc_f(float x) {
    unsigned b = __float_as_uint(x);
    return (b & 0x80000000u) ? ~b : (b | 0x80000000u);
}
__device__ __forceinline__ float dec_f(unsigned u) {
    unsigned b = (u & 0x80000000u) ? (u & 0x7FFFFFFFu) : ~u;
    return __uint_as_float(b);
}

// ---------------- zero kernels ----------------
__global__ void zero_cnt_k() {
    int i = blockIdx.x * blockDim.x + threadIdx.x;
    if (i < 2 * NN) g_cnt[i] = 0;
}
__global__ void zero_s_k() {
    for (int i = blockIdx.x * blockDim.x + threadIdx.x; i < 2 * NN * 64;
         i += gridDim.x * blockDim.x)
        g_s[i] = 0.f;
}
__global__ void zero_gat_k() {
    int i = blockIdx.x * blockDim.x + threadIdx.x;
    if (i < NN * 512) g_o512[i] = 0.f;
    if (i < NN) { g_denom[i] = 0.f; g_amax[i] = 0u; }
}

// ---------------- degree counts ----------------
__global__ void count_k(const int* __restrict__ et, const int* __restrict__ dst) {
    int e = blockIdx.x * blockDim.x + threadIdx.x;
    if (e < EE) atomicAdd(&g_cnt[et[e] * NN + dst[e]], 1);
}
__global__ void rinv_k() {
    int i = blockIdx.x * blockDim.x + threadIdx.x;
    if (i < 2 * NN) g_rinv[i] = 1.0f / fmaxf((float)g_cnt[i], 1.0f);
}

// ---------------- layer 0 (identity input shortcut) ----------------
__global__ void l0_hr_k(const float* __restrict__ basis0, const float* __restrict__ comp0) {
    int i = blockIdx.x * blockDim.x + threadIdx.x;
    if (i >= 2 * NN * 32) return;
    int r = i / (NN * 32), idx = i % (NN * 32);
    float acc = 0.f;
#pragma unroll
    for (int b = 0; b < 4; b++) acc += comp0[r * 4 + b] * basis0[b * NN * 32 + idx];
    g_hr[r * NN * 32 + idx] = acc;
}
__global__ void l0_base_k(const float* __restrict__ root0, const float* __restrict__ rbias0) {
    int i = blockIdx.x * blockDim.x + threadIdx.x;
    if (i < NN * 32) g_base[i] = root0[i] + rbias0[i & 31];
}

// ---------------- RGCN generic layers ----------------
__global__ void wcat_k(const float* __restrict__ basis, const float* __restrict__ comp,
                       int I, int O) {
    int i = blockIdx.x * blockDim.x + threadIdx.x;
    int tot = 2 * I * O;
    if (i >= tot) return;
    int r = i / (I * O), io = i % (I * O);
    float acc = 0.f;
#pragma unroll
    for (int b = 0; b < 4; b++) acc += comp[r * 4 + b] * basis[b * I * O + io];
    int irow = io / O, c = io % O;
    g_Wcat[irow * 2 * O + r * O + c] = acc;
}

// blockDim = (3*O, 4); grid = NN/4. Computes base (root) and both hr in one pass.
__global__ void rgcn_gemm_k(const float* __restrict__ root, const float* __restrict__ rbias,
                            int I, int O) {
    __shared__ float xs[4][64];
    int ty = threadIdx.y, tx = threadIdx.x;
    int n = blockIdx.x * 4 + ty;
    if (tx < I) xs[ty][tx] = g_x[n * I + tx];
    __syncthreads();
    float acc = 0.f;
    if (tx < O) {
#pragma unroll 8
        for (int i = 0; i < I; i++) acc += xs[ty][i] * root[i * O + tx];
        g_base[n * O + tx] = acc + rbias[tx];
    } else {
        int c = tx - O;
#pragma unroll 8
        for (int i = 0; i < I; i++) acc += xs[ty][i] * g_Wcat[i * 2 * O + c];
        int r = c / O, cc = c % O;
        g_hr[r * NN * O + n * O + cc] = acc;
    }
}

__global__ void rgcn_agg_k(const int* __restrict__ src, const int* __restrict__ dst,
                           const int* __restrict__ et, int O) {
    int q4 = O >> 2;
    int gid = blockIdx.x * blockDim.x + threadIdx.x;
    if (gid >= EE * q4) return;
    int e = gid / q4, q = gid % q4;
    int r = et[e];
    const float4 m = *(const float4*)&g_hr[r * NN * O + src[e] * O + q * 4];
    float* sp = &g_s[r * NN * O + dst[e] * O + q * 4];
    atomicAdd(sp + 0, m.x);
    atomicAdd(sp + 1, m.y);
    atomicAdd(sp + 2, m.z);
    atomicAdd(sp + 3, m.w);
}

__global__ void rgcn_fin_k(int O) {
    int i = blockIdx.x * blockDim.x + threadIdx.x;
    if (i >= NN * O) return;
    int n = i / O;
    float v = g_base[i] + g_s[i] * g_rinv[n] + g_s[NN * O + i] * g_rinv[NN + n];
    g_x[i] = tanhf(v);
}

// ---------------- GAT ----------------
__global__ void gat_h_k(const float* __restrict__ gw, const float* __restrict__ asrc,
                        const float* __restrict__ adst) {
    __shared__ float xs[32];
    __shared__ float reda[8], redd[8];
    int n = blockIdx.x, tid = threadIdx.x;
    if (tid < 32) xs[tid] = g_x[n * 32 + tid];
    __syncthreads();
    float a0 = 0.f, a1 = 0.f;
    int c0 = tid, c1 = tid + 256;
#pragma unroll 8
    for (int i = 0; i < 32; i++) {
        float xv = xs[i];
        a0 += xv * gw[i * 512 + c0];
        a1 += xv * gw[i * 512 + c1];
    }
    g_h[n * 512 + c0] = a0;
    g_h[n * 512 + c1] = a1;
    float pa = a0 * asrc[c0] + a1 * asrc[c1];
    float pd = a0 * adst[c0] + a1 * adst[c1];
#pragma unroll
    for (int off = 16; off; off >>= 1) {
        pa += __shfl_down_sync(0xffffffffu, pa, off);
        pd += __shfl_down_sync(0xffffffffu, pd, off);
    }
    if ((tid & 31) == 0) { reda[tid >> 5] = pa; redd[tid >> 5] = pd; }
    __syncthreads();
    if (tid == 0) {
        float sa = 0.f, sd = 0.f;
#pragma unroll
        for (int w = 0; w < 8; w++) { sa += reda[w]; sd += redd[w]; }
        g_asv[n] = sa;
        g_adv[n] = sd;
    }
}

__global__ void gat_alpha_k(const int* __restrict__ src, const int* __restrict__ dst) {
    int e = blockIdx.x * blockDim.x + threadIdx.x;
    if (e >= ET) return;
    int s, d;
    if (e < EE) { s = src[e]; d = dst[e]; } else { s = e - EE; d = s; }
    float a = g_asv[s] + g_adv[d];
    float lr = a > 0.f ? a : 0.2f * a;
    g_alpha[e] = lr;
    atomicMax(&g_amax[d], enc_f(lr));
}

__global__ void gat_ex_k(const int* __restrict__ dst) {
    int e = blockIdx.x * blockDim.x + threadIdx.x;
    if (e >= ET) return;
    int d = (e < EE) ? dst[e] : (e - EE);
    float m = dec_f(g_amax[d]);
    float ex = expf(g_alpha[e] - m);
    g_alpha[e] = ex;
    atomicAdd(&g_denom[d], ex);
}

__global__ void gat_agg_k(const int* __restrict__ src, const int* __restrict__ dst) {
    int w = (blockIdx.x * blockDim.x + threadIdx.x) >> 5;
    int lane = threadIdx.x & 31;
    if (w >= ET) return;
    int s, d;
    if (w < EE) { s = src[w]; d = dst[w]; } else { s = d = w - EE; }
    float coef = g_alpha[w] / fmaxf(g_denom[d], 1e-16f);
    const float4* hp = (const float4*)&g_h[s * 512];
    float* op = &g_o512[d * 512];
#pragma unroll
    for (int q = 0; q < 4; q++) {
        int idx = q * 32 + lane;
        float4 hv = hp[idx];
        atomicAdd(&op[idx * 4 + 0], hv.x * coef);
        atomicAdd(&op[idx * 4 + 1], hv.y * coef);
        atomicAdd(&op[idx * 4 + 2], hv.z * coef);
        atomicAdd(&op[idx * 4 + 3], hv.w * coef);
    }
}

// ---------------- edge-MLP factorization ----------------
// A = relu(xg) @ w1[:512] + b1 ; B = relu(xg) @ w1[512:]
__global__ void ab_k(const float* __restrict__ w1, const float* __restrict__ b1,
                     const float* __restrict__ gbias) {
    __shared__ float xs[8 * 512];
    int tid = threadIdx.x;
    int nb = blockIdx.x * 8;
    for (int idx = tid; idx < 8 * 512; idx += 128) {
        int t = idx >> 9, c = idx & 511;
        float v = g_o512[(nb + t) * 512 + c] + gbias[c];
        xs[idx] = v > 0.f ? v : 0.f;
    }
    __syncthreads();
    float accA[8] = {0, 0, 0, 0, 0, 0, 0, 0};
    float accB[8] = {0, 0, 0, 0, 0, 0, 0, 0};
    for (int k = 0; k < 512; k++) {
        float wA = w1[k * 128 + tid];
        float wB = w1[(k + 512) * 128 + tid];
#pragma unroll
        for (int t = 0; t < 8; t++) {
            float xv = xs[t * 512 + k];
            accA[t] += xv * wA;
            accB[t] += xv * wB;
        }
    }
#pragma unroll
    for (int t = 0; t < 8; t++) {
        g_A[(nb + t) * 128 + tid] = accA[t] + b1[tid];
        g_B[(nb + t) * 128 + tid] = accB[t];
    }
}

__global__ void final_k(const int* __restrict__ src, const int* __restrict__ dst,
                        const float* __restrict__ w2, const float* __restrict__ b2,
                        float* __restrict__ out) {
    int e = blockIdx.x * 4 + (threadIdx.x >> 5);
    int lane = threadIdx.x & 31;
    if (e >= EE) return;
    int s = src[e], d = dst[e];
    float4 a = *(const float4*)&g_A[s * 128 + lane * 4];
    float4 b = *(const float4*)&g_B[d * 128 + lane * 4];
    float4 w = *(const float4*)&w2[lane * 4];
    float h0 = fmaxf(a.x + b.x, 0.f);
    float h1 = fmaxf(a.y + b.y, 0.f);
    float h2 = fmaxf(a.z + b.z, 0.f);
    float h3 = fmaxf(a.w + b.w, 0.f);
    float sum = h0 * w.x + h1 * w.y + h2 * w.z + h3 * w.w;
#pragma unroll
    for (int off = 16; off; off >>= 1) sum += __shfl_down_sync(0xffffffffu, sum, off);
    if (lane == 0) out[e] = 1.f / (1.f + expf(-(sum + b2[0])));
}

// ---------------- host launch ----------------
extern "C" void kernel_launch(void* const* d_in, const int* in_sizes, int n_in,
                              void* d_out, int out_size) {
    // Detect input ordering: signature order (edge_index first, 2*E ints)
    // vs dict order (basis0 first, 768000 floats).
    int b = (in_sizes[0] == 2 * EE) ? 2 : 0;
    const int* eidx = (const int*)(b ? d_in[0] : d_in[24]);
    const int* etype = (const int*)(b ? d_in[1] : d_in[25]);
    const int* src = eidx;
    const int* dst = eidx + EE;
    auto F = [&](int i) { return (const float*)d_in[i]; };

    // degree counts (shared by all 4 layers)
    zero_cnt_k<<<(2 * NN + 255) / 256, 256>>>();
    count_k<<<(EE + 255) / 256, 256>>>(etype, dst);
    rinv_k<<<(2 * NN + 255) / 256, 256>>>();

    // ---- layer 0 (identity input shortcut) ----
    l0_hr_k<<<(2 * NN * 32 + 255) / 256, 256>>>(F(b + 0), F(b + 1));
    l0_base_k<<<(NN * 32 + 255) / 256, 256>>>(F(b + 2), F(b + 3));
    zero_s_k<<<512, 256>>>();
    rgcn_agg_k<<<(EE * 8 + 255) / 256, 256>>>(src, dst, etype, 32);
    rgcn_fin_k<<<(NN * 32 + 255) / 256, 256>>>(32);

    // ---- layers 1..3 ----
    const int Is[3] = {32, 64, 64};
    const int Os[3] = {64, 64, 32};
    for (int l = 1; l < 4; l++) {
        int I = Is[l - 1], O = Os[l - 1];
        wcat_k<<<(2 * I * O + 255) / 256, 256>>>(F(b + 4 * l), F(b + 4 * l + 1), I, O);
        dim3 blk(3 * O, 4);
        rgcn_gemm_k<<<NN / 4, blk>>>(F(b + 4 * l + 2), F(b + 4 * l + 3), I, O);
        zero_s_k<<<512, 256>>>();
        rgcn_agg_k<<<(EE * (O / 4) + 255) / 256, 256>>>(src, dst, etype, O);
        rgcn_fin_k<<<(NN * O + 255) / 256, 256>>>(O);
    }

    // ---- GAT ----
    gat_h_k<<<NN, 256>>>(F(b + 16), F(b + 17), F(b + 18));
    zero_gat_k<<<(NN * 512 + 255) / 256, 256>>>();
    gat_alpha_k<<<(ET + 255) / 256, 256>>>(src, dst);
    gat_ex_k<<<(ET + 255) / 256, 256>>>(dst);
    gat_agg_k<<<(ET * 32 + 255) / 256, 256>>>(src, dst);

    // ---- edge MLP (factorized) ----
    ab_k<<<NN / 8, 128>>>(F(b + 20), F(b + 21), F(b + 19));
    final_k<<<(EE + 3) / 4, 128>>>(src, dst, F(b + 22), F(b + 23), (float*)d_out);
}

// round 3
// speedup vs baseline: 1.9566x; 1.9566x over previous
#include <cuda_runtime.h>
#include <cuda_bf16.h>
#include <math.h>

#define NN 6000
#define EE 100000

// ---------------- scratch ----------------
__device__ float g_x[NN * 64];          // ping
__device__ float g_y[NN * 64];          // pong
__device__ float g_base[NN * 32];       // layer0 root term
__device__ float g_hr[2 * NN * 32];     // layer0 relation rows
__device__ float g_s[2 * NN * 64];      // per-relation aggregated inputs (mean-scaled)
__device__ float g_Wcat[64 * 128];      // [I, 2*O]
__device__ int   g_cnt[2 * NN];
__device__ float g_rinv[2 * NN];
__device__ int   g_deg[NN];
__device__ int   g_offs[NN + 1];
__device__ int   g_cur[NN];
__device__ int   g_csr[EE];             // packed src | (rel<<16)
__device__ float g_h[NN * 512];
__device__ float g_asv[NN], g_adv[NN];
__device__ float g_o512[NN * 512];
__device__ float g_A[NN * 128], g_B[NN * 128];

// ---------------- CSR build ----------------
__global__ void zero_k() {
    int i = blockIdx.x * blockDim.x + threadIdx.x;
    if (i < 2 * NN) g_cnt[i] = 0;
    if (i < NN) { g_deg[i] = 0; g_cur[i] = 0; }
}
__global__ void count_k(const int* __restrict__ et, const int* __restrict__ dst) {
    int e = blockIdx.x * blockDim.x + threadIdx.x;
    if (e < EE) {
        int d = dst[e];
        atomicAdd(&g_deg[d], 1);
        atomicAdd(&g_cnt[et[e] * NN + d], 1);
    }
}
__global__ void scan_k() {
    __shared__ int ws[32];
    int t = threadIdx.x;                 // 1024 threads
    int base = t * 6;
    int loc[6]; int s = 0;
#pragma unroll
    for (int j = 0; j < 6; j++) {
        int idx = base + j; loc[j] = s;
        s += (idx < NN) ? g_deg[idx] : 0;
    }
    int lane = t & 31, w = t >> 5;
    int v = s;
#pragma unroll
    for (int off = 1; off < 32; off <<= 1) {
        int nv = __shfl_up_sync(0xffffffffu, v, off);
        if (lane >= off) v += nv;
    }
    if (lane == 31) ws[w] = v;
    __syncthreads();
    if (w == 0) {
        int x = ws[lane];
#pragma unroll
        for (int off = 1; off < 32; off <<= 1) {
            int nv = __shfl_up_sync(0xffffffffu, x, off);
            if (lane >= off) x += nv;
        }
        ws[lane] = x;
    }
    __syncthreads();
    int excl = v - s + (w ? ws[w - 1] : 0);
#pragma unroll
    for (int j = 0; j < 6; j++) {
        int idx = base + j;
        if (idx < NN) g_offs[idx] = excl + loc[j];
    }
    if (t == 1023) g_offs[NN] = excl + s;
}
__global__ void scatter_k(const int* __restrict__ src, const int* __restrict__ dst,
                          const int* __restrict__ et) {
    int e = blockIdx.x * blockDim.x + threadIdx.x;
    if (e >= EE) return;
    int d = dst[e];
    int pos = g_offs[d] + atomicAdd(&g_cur[d], 1);
    g_csr[pos] = src[e] | (et[e] << 16);
}
__global__ void rinv_k() {
    int i = blockIdx.x * blockDim.x + threadIdx.x;
    if (i < 2 * NN) g_rinv[i] = 1.0f / fmaxf((float)g_cnt[i], 1.0f);
}

// ---------------- layer 0 (identity input shortcut) ----------------
__global__ void l0_hr_k(const float* __restrict__ basis0, const float* __restrict__ comp0) {
    int i = blockIdx.x * blockDim.x + threadIdx.x;
    if (i >= 2 * NN * 32) return;
    int r = i / (NN * 32), idx = i % (NN * 32);
    float acc = 0.f;
#pragma unroll
    for (int b = 0; b < 4; b++) acc += comp0[r * 4 + b] * basis0[b * NN * 32 + idx];
    g_hr[r * NN * 32 + idx] = acc;
}
__global__ void l0_base_k(const float* __restrict__ root0, const float* __restrict__ rbias0) {
    int i = blockIdx.x * blockDim.x + threadIdx.x;
    if (i < NN * 32) g_base[i] = root0[i] + rbias0[i & 31];
}
// warp per node, lane = channel (32). Gather-aggregate + finalize + tanh.
__global__ void l0_agg_k() {
    int n = blockIdx.x * 4 + (threadIdx.x >> 5);
    int lane = threadIdx.x & 31;
    if (n >= NN) return;
    int o = g_offs[n], e2 = g_offs[n + 1];
    float a0 = 0.f, a1 = 0.f;
    for (int p = o; p < e2; p++) {
        int pk = g_csr[p];
        float v = g_hr[(pk >> 16) * NN * 32 + (pk & 0xffff) * 32 + lane];
        if (pk & 0x10000) a1 += v; else a0 += v;
    }
    float out = g_base[n * 32 + lane] + a0 * g_rinv[n] + a1 * g_rinv[NN + n];
    g_x[n * 32 + lane] = tanhf(out);
}

// ---------------- RGCN layers 1..3 ----------------
__global__ void wcat_k(const float* __restrict__ basis, const float* __restrict__ comp,
                       int I, int O) {
    int i = blockIdx.x * blockDim.x + threadIdx.x;
    if (i >= 2 * I * O) return;
    int r = i / (I * O), io = i % (I * O);
    float acc = 0.f;
#pragma unroll
    for (int b = 0; b < 4; b++) acc += comp[r * 4 + b] * basis[b * I * O + io];
    int irow = io / O, c = io % O;
    g_Wcat[irow * 2 * O + r * O + c] = acc;
}
// warp per node: aggregate input features per relation (mean-scaled).
__global__ void aggx_k(int I, int inflag) {
    const float* xin = inflag ? g_y : g_x;
    int n = blockIdx.x * 4 + (threadIdx.x >> 5);
    int lane = threadIdx.x & 31;
    if (n >= NN) return;
    int o = g_offs[n], e2 = g_offs[n + 1];
    float a00 = 0.f, a01 = 0.f, a10 = 0.f, a11 = 0.f;
    for (int p = o; p < e2; p++) {
        int pk = g_csr[p];
        int s = pk & 0xffff;
        float v0 = xin[s * I + lane];
        float v1 = (I == 64) ? xin[s * I + lane + 32] : 0.f;
        if (pk & 0x10000) { a10 += v0; a11 += v1; }
        else              { a00 += v0; a01 += v1; }
    }
    float r0 = g_rinv[n], r1 = g_rinv[NN + n];
    g_s[n * I + lane] = a00 * r0;
    g_s[NN * I + n * I + lane] = a10 * r1;
    if (I == 64) {
        g_s[n * I + lane + 32] = a01 * r0;
        g_s[NN * I + n * I + lane + 32] = a11 * r1;
    }
}
// block: (O, 4) threads, 4 nodes. out = tanh(x@root + agg0@W0 + agg1@W1 + bias)
__global__ void rgcn_gemm2_k(const float* __restrict__ root, const float* __restrict__ rbias,
                             int I, int O, int inflag) {
    __shared__ float xs[4][64], a0s[4][64], a1s[4][64];
    const float* xin = inflag ? g_y : g_x;
    float* xout = inflag ? g_x : g_y;
    int ty = threadIdx.y, tx = threadIdx.x;
    int n = blockIdx.x * 4 + ty;
    for (int i = tx; i < I; i += O) {
        xs[ty][i]  = xin[n * I + i];
        a0s[ty][i] = g_s[n * I + i];
        a1s[ty][i] = g_s[NN * I + n * I + i];
    }
    __syncthreads();
    float acc = rbias[tx];
#pragma unroll 8
    for (int i = 0; i < I; i++) {
        acc += xs[ty][i] * root[i * O + tx];
        acc += a0s[ty][i] * g_Wcat[i * 2 * O + tx];
        acc += a1s[ty][i] * g_Wcat[i * 2 * O + O + tx];
    }
    xout[n * O + tx] = tanhf(acc);
}

// ---------------- GAT ----------------
__global__ void gat_h_k(const float* __restrict__ gw, const float* __restrict__ asrc,
                        const float* __restrict__ adst) {
    __shared__ float xs[32];
    __shared__ float reda[8], redd[8];
    int n = blockIdx.x, tid = threadIdx.x;
    if (tid < 32) xs[tid] = g_y[n * 32 + tid];   // layer3 output lives in g_y
    __syncthreads();
    float a0 = 0.f, a1 = 0.f;
    int c0 = tid, c1 = tid + 256;
#pragma unroll 8
    for (int i = 0; i < 32; i++) {
        float xv = xs[i];
        a0 += xv * gw[i * 512 + c0];
        a1 += xv * gw[i * 512 + c1];
    }
    g_h[n * 512 + c0] = a0;
    g_h[n * 512 + c1] = a1;
    float pa = a0 * asrc[c0] + a1 * asrc[c1];
    float pd = a0 * adst[c0] + a1 * adst[c1];
#pragma unroll
    for (int off = 16; off; off >>= 1) {
        pa += __shfl_down_sync(0xffffffffu, pa, off);
        pd += __shfl_down_sync(0xffffffffu, pd, off);
    }
    if ((tid & 31) == 0) { reda[tid >> 5] = pa; redd[tid >> 5] = pd; }
    __syncthreads();
    if (tid == 0) {
        float sa = 0.f, sd = 0.f;
#pragma unroll
        for (int w = 0; w < 8; w++) { sa += reda[w]; sd += redd[w]; }
        g_asv[n] = sa;
        g_adv[n] = sd;
    }
}
// block(128) per node: softmax over incoming edges + self-loop, then gather-weighted sum.
__global__ void gat_node_k() {
    __shared__ float sal[2048];
    __shared__ float red[128];
    int n = blockIdx.x, tid = threadIdx.x;
    int o = g_offs[n];
    int deg = g_offs[n + 1] - o;
    if (deg > 2048) deg = 2048;
    float advn = g_adv[n];
    float lm = -1e30f;
    for (int p = tid; p < deg; p += 128) {
        int s = g_csr[o + p] & 0xffff;
        float a = g_asv[s] + advn;
        a = a > 0.f ? a : 0.2f * a;
        sal[p] = a;
        lm = fmaxf(lm, a);
    }
    float als = g_asv[n] + advn;
    als = als > 0.f ? als : 0.2f * als;
    lm = fmaxf(lm, als);
    red[tid] = lm; __syncthreads();
    for (int st = 64; st; st >>= 1) {
        if (tid < st) red[tid] = fmaxf(red[tid], red[tid + st]);
        __syncthreads();
    }
    float m = red[0];
    __syncthreads();
    float ls = 0.f;
    for (int p = tid; p < deg; p += 128) {
        float ex = expf(sal[p] - m);
        sal[p] = ex;
        ls += ex;
    }
    float exs = expf(als - m);
    if (tid == 0) ls += exs;
    red[tid] = ls; __syncthreads();
    for (int st = 64; st; st >>= 1) {
        if (tid < st) red[tid] += red[tid + st];
        __syncthreads();
    }
    float invden = 1.f / fmaxf(red[0], 1e-16f);
    // weighted sum: thread tid owns cols 4*tid..4*tid+3
    float cs = exs * invden;
    float4 hv = ((const float4*)&g_h[n * 512])[tid];
    float4 acc;
    acc.x = cs * hv.x; acc.y = cs * hv.y; acc.z = cs * hv.z; acc.w = cs * hv.w;
    for (int p = 0; p < deg; p++) {
        int s = g_csr[o + p] & 0xffff;
        float c = sal[p] * invden;
        float4 h4 = ((const float4*)&g_h[s * 512])[tid];
        acc.x += c * h4.x; acc.y += c * h4.y; acc.z += c * h4.z; acc.w += c * h4.w;
    }
    ((float4*)&g_o512[n * 512])[tid] = acc;
}

// ---------------- edge-MLP node GEMM: out[N,256] = relu(o512+gbias) @ Wab ----------------
#define BM 64
#define BN 64
#define BK 16
__global__ void ab_gemm_k(const float* __restrict__ w1, const float* __restrict__ b1,
                          const float* __restrict__ gbias) {
    __shared__ float As[BK][BM + 4];
    __shared__ float Bs[BK][BN];
    int tid = threadIdx.x;                 // 256
    int bm = blockIdx.x * BM, bn = blockIdx.y * BN;
    int tx = tid & 15, ty = tid >> 4;
    float acc[4][4] = {};
    for (int k0 = 0; k0 < 512; k0 += BK) {
#pragma unroll
        for (int i = 0; i < 4; i++) {
            int id = i * 256 + tid;
            int kk = id >> 6, mm = id & 63;
            int gm = bm + mm;
            float v = (gm < NN) ? g_o512[gm * 512 + k0 + kk] + gbias[k0 + kk] : 0.f;
            As[kk][mm] = fmaxf(v, 0.f);
            int nn2 = id & 63;
            int gn = bn + nn2;
            int row = k0 + kk + ((gn >= 128) ? 512 : 0);
            int col = gn & 127;
            Bs[kk][nn2] = w1[row * 128 + col];
        }
        __syncthreads();
#pragma unroll
        for (int kk = 0; kk < BK; kk++) {
            float a[4], b[4];
#pragma unroll
            for (int j = 0; j < 4; j++) { a[j] = As[kk][ty * 4 + j]; b[j] = Bs[kk][tx * 4 + j]; }
#pragma unroll
            for (int i = 0; i < 4; i++)
#pragma unroll
                for (int j = 0; j < 4; j++) acc[i][j] += a[i] * b[j];
        }
        __syncthreads();
    }
#pragma unroll
    for (int i = 0; i < 4; i++) {
        int gm = bm + ty * 4 + i;
        if (gm >= NN) continue;
#pragma unroll
        for (int j = 0; j < 4; j++) {
            int gn = bn + tx * 4 + j;
            if (gn < 128) g_A[gm * 128 + gn] = acc[i][j] + b1[gn];
            else          g_B[gm * 128 + (gn - 128)] = acc[i][j];
        }
    }
}

__global__ void final_k(const int* __restrict__ src, const int* __restrict__ dst,
                        const float* __restrict__ w2, const float* __restrict__ b2,
                        float* __restrict__ out) {
    int e = blockIdx.x * 4 + (threadIdx.x >> 5);
    int lane = threadIdx.x & 31;
    if (e >= EE) return;
    int s = src[e], d = dst[e];
    float4 a = *(const float4*)&g_A[s * 128 + lane * 4];
    float4 b = *(const float4*)&g_B[d * 128 + lane * 4];
    float4 w = *(const float4*)&w2[lane * 4];
    float sum = fmaxf(a.x + b.x, 0.f) * w.x + fmaxf(a.y + b.y, 0.f) * w.y +
                fmaxf(a.z + b.z, 0.f) * w.z + fmaxf(a.w + b.w, 0.f) * w.w;
#pragma unroll
    for (int off = 16; off; off >>= 1) sum += __shfl_down_sync(0xffffffffu, sum, off);
    if (lane == 0) out[e] = 1.f / (1.f + expf(-(sum + b2[0])));
}

// ---------------- host ----------------
extern "C" void kernel_launch(void* const* d_in, const int* in_sizes, int n_in,
                              void* d_out, int out_size) {
    int b = (in_sizes[0] == 2 * EE) ? 2 : 0;
    const int* eidx = (const int*)(b ? d_in[0] : d_in[24]);
    const int* etype = (const int*)(b ? d_in[1] : d_in[25]);
    const int* src = eidx;
    const int* dst = eidx + EE;
    auto F = [&](int i) { return (const float*)d_in[i]; };

    // CSR build + degree counts
    zero_k<<<(2 * NN + 255) / 256, 256>>>();
    count_k<<<(EE + 255) / 256, 256>>>(etype, dst);
    scan_k<<<1, 1024>>>();
    scatter_k<<<(EE + 255) / 256, 256>>>(src, dst, etype);
    rinv_k<<<(2 * NN + 255) / 256, 256>>>();

    // layer 0
    l0_hr_k<<<(2 * NN * 32 + 255) / 256, 256>>>(F(b + 0), F(b + 1));
    l0_base_k<<<(NN * 32 + 255) / 256, 256>>>(F(b + 2), F(b + 3));
    l0_agg_k<<<NN / 4, 128>>>();

    // layers 1..3 (ping-pong: L1 x->y, L2 y->x, L3 x->y)
    const int Is[3] = {32, 64, 64};
    const int Os[3] = {64, 64, 32};
    const int inflags[3] = {0, 1, 0};
    for (int l = 1; l < 4; l++) {
        int I = Is[l - 1], O = Os[l - 1];
        wcat_k<<<(2 * I * O + 255) / 256, 256>>>(F(b + 4 * l), F(b + 4 * l + 1), I, O);
        aggx_k<<<NN / 4, 128>>>(I, inflags[l - 1]);
        dim3 blk(O, 4);
        rgcn_gemm2_k<<<NN / 4, blk>>>(F(b + 4 * l + 2), F(b + 4 * l + 3), I, O, inflags[l - 1]);
    }

    // GAT
    gat_h_k<<<NN, 256>>>(F(b + 16), F(b + 17), F(b + 18));
    gat_node_k<<<NN, 128>>>();

    // edge MLP
    dim3 abgrid((NN + BM - 1) / BM, 256 / BN);
    ab_gemm_k<<<abgrid, 256>>>(F(b + 20), F(b + 21), F(b + 19));
    final_k<<<(EE + 3) / 4, 128>>>(src, dst, F(b + 22), F(b + 23), (float*)d_out);
}